// round 6
// baseline (speedup 1.0000x reference)
#include <cuda_runtime.h>
#include <math.h>

// Problem constants (fixed by the dataset)
#define B_   4
#define LP_  256
#define LW_  200
#define D_   768
#define D4_  (D_/4)      // 192 float4 per row
#define NCH_ 37          // word-chunks per batch (15 chunks of 6 + 22 chunks of 5)
#define WMAX_ 6
#define NQ_  4           // piece-quarters
#define NT_  (NQ_*D4_)   // 768 threads per block
#define PPQ_ (LP_/NQ_)   // 64 pieces per quarter

#define MIN_BLOCKS 768

__device__ float g_partial_min[MIN_BLOCKS];

// ---------------- global-min partial reduction ----------------
// grid 768 x 256: exactly one float4 per thread, no serial loop.
__global__ __launch_bounds__(256) void partial_min_kernel(
    const float4* __restrict__ x, int n4)
{
    int i = blockIdx.x * blockDim.x + threadIdx.x;
    float m = INFINITY;
    if (i < n4) {
        float4 v = x[i];
        m = fminf(fminf(v.x, v.y), fminf(v.z, v.w));
    }
    __shared__ float s[256];
    int t = threadIdx.x;
    s[t] = m;
    __syncthreads();
    for (int off = 128; off > 0; off >>= 1) {
        if (t < off) s[t] = fminf(s[t], s[t + off]);
        __syncthreads();
    }
    if (t == 0) g_partial_min[blockIdx.x] = s[0];
}

// ---------------- main: masked max-pool ----------------
// grid: 148 blocks = 4 batches x 37 word-chunks (one block per SM).
// block: 768 threads = 4 piece-quarters x 192 d-slots.
__global__ __launch_bounds__(NT_) void word_max_kernel(
    const float* __restrict__ emb,      // [B, Lp, D]
    const int*   __restrict__ p2w,      // [B, Lw, Lp]
    float*       __restrict__ out)      // [B, Lw, D]
{
    __shared__ float4 sacc[2][WMAX_][D4_];      // quarter partials (36.9 KB)
    __shared__ unsigned char smask[LP_];
    __shared__ float sred[MIN_BLOCKS];          // 3 KB

    const int tid = threadIdx.x;
    const int blk = blockIdx.x;
    const int b   = blk / NCH_;
    const int c   = blk % NCH_;
    const int w0  = (c < 15) ? c * 6 : 90 + (c - 15) * 5;
    const int nw  = (c < 15) ? 6 : 5;

    // --- reduce global min from the 768 partials (redundant per block) ---
    sred[tid] = g_partial_min[tid];
    __syncthreads();
    if (tid < 256) sred[tid] = fminf(sred[tid], sred[tid + 512]);
    __syncthreads();
    for (int off = 256; off > 0; off >>= 1) {
        if (tid < off) sred[tid] = fminf(sred[tid], sred[tid + off]);
        __syncthreads();
    }

    // --- build per-piece mask bitmap (first 256 threads) ---
    if (tid < LP_) {
        const int p = tid;
        unsigned m = 0;
        const int* row = p2w + ((size_t)(b * LW_ + w0)) * LP_ + p;
        #pragma unroll
        for (int j = 0; j < WMAX_; j++) {
            if (j < nw && row[(size_t)j * LP_] != 0) m |= (1u << j);
        }
        smask[p] = (unsigned char)m;
    }
    __syncthreads();

    const float gmin = sred[0];
    const int q  = tid / D4_;        // piece-quarter 0..3
    const int dt = tid % D4_;        // float4 slot in D
    const int p0 = q * PPQ_;

    float4 acc[WMAX_];
    #pragma unroll
    for (int j = 0; j < WMAX_; j++) acc[j] = make_float4(gmin, gmin, gmin, gmin);

    const float4* erow = reinterpret_cast<const float4*>(emb)
                         + (size_t)b * LP_ * D4_ + dt;

    // 64 pieces per quarter, 4 at a time: 4 unconditional loads (MLP=4),
    // then mask-predicated fmax into 6x4 independent accumulators.
    for (int p = p0; p < p0 + PPQ_; p += 4) {
        unsigned mq = *reinterpret_cast<const unsigned*>(&smask[p]);
        float4 v0 = erow[(size_t)(p + 0) * D4_];
        float4 v1 = erow[(size_t)(p + 1) * D4_];
        float4 v2 = erow[(size_t)(p + 2) * D4_];
        float4 v3 = erow[(size_t)(p + 3) * D4_];

        #pragma unroll
        for (int qq = 0; qq < 4; qq++) {
            float4 v = (qq == 0) ? v0 : (qq == 1) ? v1 : (qq == 2) ? v2 : v3;
            #pragma unroll
            for (int j = 0; j < WMAX_; j++) {
                if (mq & (1u << (8 * qq + j))) {
                    acc[j].x = fmaxf(acc[j].x, v.x);
                    acc[j].y = fmaxf(acc[j].y, v.y);
                    acc[j].z = fmaxf(acc[j].z, v.z);
                    acc[j].w = fmaxf(acc[j].w, v.w);
                }
            }
        }
    }

    // --- combine quarters: {2,3} -> smem; {0,1} merge; 1 -> smem; 0 final ---
    if (q >= 2) {
        #pragma unroll
        for (int j = 0; j < WMAX_; j++) sacc[q - 2][j][dt] = acc[j];
    }
    __syncthreads();
    if (q < 2) {
        #pragma unroll
        for (int j = 0; j < WMAX_; j++) {
            float4 o = sacc[q][j][dt];
            acc[j].x = fmaxf(acc[j].x, o.x);
            acc[j].y = fmaxf(acc[j].y, o.y);
            acc[j].z = fmaxf(acc[j].z, o.z);
            acc[j].w = fmaxf(acc[j].w, o.w);
        }
        if (q == 1) {
            #pragma unroll
            for (int j = 0; j < WMAX_; j++) sacc[1][j][dt] = acc[j];
        }
    }
    __syncthreads();
    if (q == 0) {
        float4* out4 = reinterpret_cast<float4*>(out)
                       + ((size_t)(b * LW_ + w0)) * D4_ + dt;
        #pragma unroll
        for (int j = 0; j < WMAX_; j++) {
            if (j < nw) {
                float4 o = sacc[1][j][dt];
                o.x = fmaxf(o.x, acc[j].x);
                o.y = fmaxf(o.y, acc[j].y);
                o.z = fmaxf(o.z, acc[j].z);
                o.w = fmaxf(o.w, acc[j].w);
                out4[(size_t)j * D4_] = o;
            }
        }
    }
}

extern "C" void kernel_launch(void* const* d_in, const int* in_sizes, int n_in,
                              void* d_out, int out_size) {
    const float* emb = (const float*)d_in[0];   // [4,256,768] f32
    const int*   p2w = (const int*)d_in[1];     // [4,200,256] i32
    float*       out = (float*)d_out;           // [4,200,768] f32

    const int n4 = (B_ * LP_ * D_) / 4;         // 196608 = 768 * 256
    partial_min_kernel<<<MIN_BLOCKS, 256>>>((const float4*)emb, n4);
    word_max_kernel<<<B_ * NCH_, NT_>>>(emb, p2w, out);
}

// round 9
// speedup vs baseline: 1.2009x; 1.2009x over previous
#include <cuda_runtime.h>
#include <math.h>

// Problem constants (fixed by the dataset)
#define B_   4
#define LP_  256
#define LW_  200
#define D_   768
#define D4_  (D_/4)      // 192 float4 per row
#define NCH_ 37          // word-chunks per batch (15 chunks of 6 + 22 chunks of 5)
#define WMAX_ 6
#define NQ_  4           // piece-quarters
#define NT_  (NQ_*D4_)   // 768 threads per block
#define PPQ_ (LP_/NQ_)   // 64 pieces per quarter

#define MIN_BLOCKS 768

__device__ float g_partial_min[MIN_BLOCKS];
__device__ float g_min_val;

// ---------------- global-min partial reduction ----------------
// grid 768 x 256: exactly one float4 per thread.
__global__ __launch_bounds__(256) void partial_min_kernel(
    const float4* __restrict__ x, int n4)
{
    int i = blockIdx.x * blockDim.x + threadIdx.x;
    float m = INFINITY;
    if (i < n4) {
        float4 v = x[i];
        m = fminf(fminf(v.x, v.y), fminf(v.z, v.w));
    }
    __shared__ float s[256];
    int t = threadIdx.x;
    s[t] = m;
    __syncthreads();
    for (int off = 128; off > 0; off >>= 1) {
        if (t < off) s[t] = fminf(s[t], s[t + off]);
        __syncthreads();
    }
    if (t == 0) g_partial_min[blockIdx.x] = s[0];
}

// ---------------- final min: 768 partials -> scalar ----------------
__global__ __launch_bounds__(256) void final_min_kernel() {
    int t = threadIdx.x;
    float m = fminf(fminf(g_partial_min[t], g_partial_min[t + 256]),
                    g_partial_min[t + 512]);
    __shared__ float s[256];
    s[t] = m;
    __syncthreads();
    for (int off = 128; off > 0; off >>= 1) {
        if (t < off) s[t] = fminf(s[t], s[t + off]);
        __syncthreads();
    }
    if (t == 0) g_min_val = s[0];
}

// ---------------- main: masked max-pool ----------------
// grid: 148 blocks = 4 batches x 37 word-chunks (one block per SM).
// block: 768 threads = 4 piece-quarters x 192 d-slots. launch_bounds(768,1)
// gives an 84-reg cap so the 6x float4 accumulators + 8 in-flight rows
// stay in registers (R5's 40-reg cap caused local spills).
__global__ __launch_bounds__(NT_, 1) void word_max_kernel(
    const float* __restrict__ emb,      // [B, Lp, D]
    const int*   __restrict__ p2w,      // [B, Lw, Lp]
    float*       __restrict__ out)      // [B, Lw, D]
{
    __shared__ float4 sacc[2][WMAX_][D4_];      // quarter partials (36.9 KB)
    __shared__ unsigned char smask[LP_];

    const int tid = threadIdx.x;
    const int blk = blockIdx.x;
    const int b   = blk / NCH_;
    const int c   = blk % NCH_;
    const int w0  = (c < 15) ? c * 6 : 90 + (c - 15) * 5;
    const int nw  = (c < 15) ? 6 : 5;

    // --- build per-piece mask bitmap (first 256 threads) ---
    if (tid < LP_) {
        const int p = tid;
        unsigned m = 0;
        const int* row = p2w + ((size_t)(b * LW_ + w0)) * LP_ + p;
        #pragma unroll
        for (int j = 0; j < WMAX_; j++) {
            if (j < nw && row[(size_t)j * LP_] != 0) m |= (1u << j);
        }
        smask[p] = (unsigned char)m;
    }
    __syncthreads();

    const float gmin = g_min_val;
    const int q  = tid / D4_;        // piece-quarter 0..3
    const int dt = tid % D4_;        // float4 slot in D
    const int p0 = q * PPQ_;

    float4 acc[WMAX_];
    #pragma unroll
    for (int j = 0; j < WMAX_; j++) acc[j] = make_float4(gmin, gmin, gmin, gmin);

    const float4* erow = reinterpret_cast<const float4*>(emb)
                         + (size_t)b * LP_ * D4_ + dt;

    // 64 pieces per quarter, 8 at a time: 8 unconditional loads in flight
    // (MLP=8), then mask-predicated fmax into 6x4 accumulators.
    for (int p = p0; p < p0 + PPQ_; p += 8) {
        unsigned m0 = *reinterpret_cast<const unsigned*>(&smask[p]);
        unsigned m1 = *reinterpret_cast<const unsigned*>(&smask[p + 4]);
        float4 v0 = erow[(size_t)(p + 0) * D4_];
        float4 v1 = erow[(size_t)(p + 1) * D4_];
        float4 v2 = erow[(size_t)(p + 2) * D4_];
        float4 v3 = erow[(size_t)(p + 3) * D4_];
        float4 v4 = erow[(size_t)(p + 4) * D4_];
        float4 v5 = erow[(size_t)(p + 5) * D4_];
        float4 v6 = erow[(size_t)(p + 6) * D4_];
        float4 v7 = erow[(size_t)(p + 7) * D4_];

        #pragma unroll
        for (int qq = 0; qq < 8; qq++) {
            float4 v = (qq == 0) ? v0 : (qq == 1) ? v1 : (qq == 2) ? v2 :
                       (qq == 3) ? v3 : (qq == 4) ? v4 : (qq == 5) ? v5 :
                       (qq == 6) ? v6 : v7;
            unsigned m = (qq < 4) ? m0 : m1;
            unsigned sh = 8 * (qq & 3);
            #pragma unroll
            for (int j = 0; j < WMAX_; j++) {
                if (m & (1u << (sh + j))) {
                    acc[j].x = fmaxf(acc[j].x, v.x);
                    acc[j].y = fmaxf(acc[j].y, v.y);
                    acc[j].z = fmaxf(acc[j].z, v.z);
                    acc[j].w = fmaxf(acc[j].w, v.w);
                }
            }
        }
    }

    // --- combine quarters: {2,3} -> smem; {0,1} merge; 1 -> smem; 0 final ---
    if (q >= 2) {
        #pragma unroll
        for (int j = 0; j < WMAX_; j++) sacc[q - 2][j][dt] = acc[j];
    }
    __syncthreads();
    if (q < 2) {
        #pragma unroll
        for (int j = 0; j < WMAX_; j++) {
            float4 o = sacc[q][j][dt];
            acc[j].x = fmaxf(acc[j].x, o.x);
            acc[j].y = fmaxf(acc[j].y, o.y);
            acc[j].z = fmaxf(acc[j].z, o.z);
            acc[j].w = fmaxf(acc[j].w, o.w);
        }
        if (q == 1) {
            #pragma unroll
            for (int j = 0; j < WMAX_; j++) sacc[1][j][dt] = acc[j];
        }
    }
    __syncthreads();
    if (q == 0) {
        float4* out4 = reinterpret_cast<float4*>(out)
                       + ((size_t)(b * LW_ + w0)) * D4_ + dt;
        #pragma unroll
        for (int j = 0; j < WMAX_; j++) {
            if (j < nw) {
                float4 o = sacc[1][j][dt];
                o.x = fmaxf(o.x, acc[j].x);
                o.y = fmaxf(o.y, acc[j].y);
                o.z = fmaxf(o.z, acc[j].z);
                o.w = fmaxf(o.w, acc[j].w);
                out4[(size_t)j * D4_] = o;
            }
        }
    }
}

extern "C" void kernel_launch(void* const* d_in, const int* in_sizes, int n_in,
                              void* d_out, int out_size) {
    const float* emb = (const float*)d_in[0];   // [4,256,768] f32
    const int*   p2w = (const int*)d_in[1];     // [4,200,256] i32
    float*       out = (float*)d_out;           // [4,200,768] f32

    const int n4 = (B_ * LP_ * D_) / 4;         // 196608 = 768 * 256
    partial_min_kernel<<<MIN_BLOCKS, 256>>>((const float4*)emb, n4);
    final_min_kernel<<<1, 256>>>();
    word_max_kernel<<<B_ * NCH_, NT_>>>(emb, p2w, out);
}

// round 12
// speedup vs baseline: 1.3249x; 1.1032x over previous
#include <cuda_runtime.h>
#include <math.h>

// Problem constants (fixed by the dataset)
#define B_   4
#define LP_  256
#define LW_  200
#define D_   768
#define D4_  (D_/4)      // 192 float4 per row
#define NCH_ 37          // word-chunks per batch (15 chunks of 6 + 22 chunks of 5)
#define WMAX_ 6
#define NQ_  4           // piece-quarters
#define NT_  (NQ_*D4_)   // 768 threads per block
#define PPQ_ (LP_/NQ_)   // 64 pieces per quarter

#define MIN_BLOCKS 148
#define MIN_THREADS 1024

__device__ float g_partial_min[MIN_BLOCKS];

// ---------------- global-min partial reduction ----------------
// 148 blocks x 1024 threads, grid-stride: 1-2 float4 per thread,
// warp-shfl reduce (no barrier tree), one smem fold.
__global__ __launch_bounds__(MIN_THREADS) void partial_min_kernel(
    const float4* __restrict__ x, int n4)
{
    const int stride = MIN_BLOCKS * MIN_THREADS;   // 151552
    int i = blockIdx.x * MIN_THREADS + threadIdx.x;
    float m = INFINITY;
    if (i < n4) {
        float4 v = x[i];
        m = fminf(fminf(v.x, v.y), fminf(v.z, v.w));
    }
    i += stride;
    if (i < n4) {
        float4 v = x[i];
        m = fminf(m, fminf(fminf(v.x, v.y), fminf(v.z, v.w)));
    }
    // warp reduce
    #pragma unroll
    for (int off = 16; off > 0; off >>= 1)
        m = fminf(m, __shfl_xor_sync(0xFFFFFFFFu, m, off));

    __shared__ float s[32];
    const int wid = threadIdx.x >> 5;
    const int lid = threadIdx.x & 31;
    if (lid == 0) s[wid] = m;
    __syncthreads();
    if (wid == 0) {
        m = s[lid];
        #pragma unroll
        for (int off = 16; off > 0; off >>= 1)
            m = fminf(m, __shfl_xor_sync(0xFFFFFFFFu, m, off));
        if (lid == 0) g_partial_min[blockIdx.x] = m;
    }
}

// ---------------- main: masked max-pool ----------------
// grid: 148 blocks = 4 batches x 37 word-chunks (one block per SM).
// block: 768 threads = 4 piece-quarters x 192 d-slots.
__global__ __launch_bounds__(NT_, 1) void word_max_kernel(
    const float* __restrict__ emb,      // [B, Lp, D]
    const int*   __restrict__ p2w,      // [B, Lw, Lp]
    float*       __restrict__ out)      // [B, Lw, D]
{
    __shared__ float4 sacc[2][WMAX_][D4_];      // quarter partials (36.9 KB)
    __shared__ unsigned char smask[LP_];
    __shared__ float sgmin;

    const int tid = threadIdx.x;
    const int blk = blockIdx.x;
    const int b   = blk / NCH_;
    const int c   = blk % NCH_;
    const int w0  = (c < 15) ? c * 6 : 90 + (c - 15) * 5;
    const int nw  = (c < 15) ? 6 : 5;

    // --- warp 0: reduce the 148 min-partials; threads 256..511: build mask ---
    if (tid < 32) {
        float m = INFINITY;
        #pragma unroll
        for (int k = tid; k < MIN_BLOCKS; k += 32)
            m = fminf(m, g_partial_min[k]);
        #pragma unroll
        for (int off = 16; off > 0; off >>= 1)
            m = fminf(m, __shfl_xor_sync(0xFFFFFFFFu, m, off));
        if (tid == 0) sgmin = m;
    } else if (tid >= 256 && tid < 256 + LP_) {
        const int p = tid - 256;
        unsigned m = 0;
        const int* row = p2w + ((size_t)(b * LW_ + w0)) * LP_ + p;
        #pragma unroll
        for (int j = 0; j < WMAX_; j++) {
            if (j < nw && row[(size_t)j * LP_] != 0) m |= (1u << j);
        }
        smask[p] = (unsigned char)m;
    }
    __syncthreads();

    const float gmin = sgmin;
    const int q  = tid / D4_;        // piece-quarter 0..3
    const int dt = tid % D4_;        // float4 slot in D
    const int p0 = q * PPQ_;

    float4 acc[WMAX_];
    #pragma unroll
    for (int j = 0; j < WMAX_; j++) acc[j] = make_float4(gmin, gmin, gmin, gmin);

    const float4* erow = reinterpret_cast<const float4*>(emb)
                         + (size_t)b * LP_ * D4_ + dt;

    // 64 pieces per quarter, 8 at a time: 8 unconditional loads in flight
    // (MLP=8), then mask-predicated fmax into 6x4 accumulators.
    for (int p = p0; p < p0 + PPQ_; p += 8) {
        unsigned m0 = *reinterpret_cast<const unsigned*>(&smask[p]);
        unsigned m1 = *reinterpret_cast<const unsigned*>(&smask[p + 4]);
        float4 v0 = erow[(size_t)(p + 0) * D4_];
        float4 v1 = erow[(size_t)(p + 1) * D4_];
        float4 v2 = erow[(size_t)(p + 2) * D4_];
        float4 v3 = erow[(size_t)(p + 3) * D4_];
        float4 v4 = erow[(size_t)(p + 4) * D4_];
        float4 v5 = erow[(size_t)(p + 5) * D4_];
        float4 v6 = erow[(size_t)(p + 6) * D4_];
        float4 v7 = erow[(size_t)(p + 7) * D4_];

        #pragma unroll
        for (int qq = 0; qq < 8; qq++) {
            float4 v = (qq == 0) ? v0 : (qq == 1) ? v1 : (qq == 2) ? v2 :
                       (qq == 3) ? v3 : (qq == 4) ? v4 : (qq == 5) ? v5 :
                       (qq == 6) ? v6 : v7;
            unsigned m = (qq < 4) ? m0 : m1;
            unsigned sh = 8 * (qq & 3);
            #pragma unroll
            for (int j = 0; j < WMAX_; j++) {
                if (m & (1u << (sh + j))) {
                    acc[j].x = fmaxf(acc[j].x, v.x);
                    acc[j].y = fmaxf(acc[j].y, v.y);
                    acc[j].z = fmaxf(acc[j].z, v.z);
                    acc[j].w = fmaxf(acc[j].w, v.w);
                }
            }
        }
    }

    // --- combine quarters: {2,3} -> smem; {0,1} merge; 1 -> smem; 0 final ---
    if (q >= 2) {
        #pragma unroll
        for (int j = 0; j < WMAX_; j++) sacc[q - 2][j][dt] = acc[j];
    }
    __syncthreads();
    if (q < 2) {
        #pragma unroll
        for (int j = 0; j < WMAX_; j++) {
            float4 o = sacc[q][j][dt];
            acc[j].x = fmaxf(acc[j].x, o.x);
            acc[j].y = fmaxf(acc[j].y, o.y);
            acc[j].z = fmaxf(acc[j].z, o.z);
            acc[j].w = fmaxf(acc[j].w, o.w);
        }
        if (q == 1) {
            #pragma unroll
            for (int j = 0; j < WMAX_; j++) sacc[1][j][dt] = acc[j];
        }
    }
    __syncthreads();
    if (q == 0) {
        float4* out4 = reinterpret_cast<float4*>(out)
                       + ((size_t)(b * LW_ + w0)) * D4_ + dt;
        #pragma unroll
        for (int j = 0; j < WMAX_; j++) {
            if (j < nw) {
                float4 o = sacc[1][j][dt];
                o.x = fmaxf(o.x, acc[j].x);
                o.y = fmaxf(o.y, acc[j].y);
                o.z = fmaxf(o.z, acc[j].z);
                o.w = fmaxf(o.w, acc[j].w);
                out4[(size_t)j * D4_] = o;
            }
        }
    }
}

extern "C" void kernel_launch(void* const* d_in, const int* in_sizes, int n_in,
                              void* d_out, int out_size) {
    const float* emb = (const float*)d_in[0];   // [4,256,768] f32
    const int*   p2w = (const int*)d_in[1];     // [4,200,256] i32
    float*       out = (float*)d_out;           // [4,200,768] f32

    const int n4 = (B_ * LP_ * D_) / 4;         // 196608
    partial_min_kernel<<<MIN_BLOCKS, MIN_THREADS>>>((const float4*)emb, n4);
    word_max_kernel<<<B_ * NCH_, NT_>>>(emb, p2w, out);
}